// round 1
// baseline (speedup 1.0000x reference)
#include <cuda_runtime.h>
#include <cstddef>

// Problem constants
#define Bb 2
#define Ss 2048
#define Dd 512
#define Hh 8
#define DKk 64
#define BH (Bb*Hh)          // 16
#define MM (Bb*Ss)          // 4096 rows for projections
#define SCALE 0.125f        // 1/sqrt(64)

// Scratch (device globals; no allocation allowed)
__device__ float g_Q[BH * Ss * DKk];   // [b,h,s,dk]
__device__ float g_K[BH * Ss * DKk];
__device__ float g_V[BH * Ss * DKk];
__device__ float g_O[MM * Dd];         // merged heads [b,s,d]

// ---------------------------------------------------------------------------
// Projection GEMM (NT): C[m,n] = sum_k X[m,k] * W[n,k]
// M=4096, N=512, K=512. Tile 64x64, KT=32, 256 threads, 4x4 microtile.
// mode 0: write head-split [b,h,s,dk]; mode 1: plain row-major [m,n].
// ---------------------------------------------------------------------------
__global__ __launch_bounds__(256) void proj_kernel(
    const float* __restrict__ X, const float* __restrict__ W,
    float* __restrict__ out, int K, int mode)
{
    __shared__ float As[32][68];
    __shared__ float Bs[32][68];
    const int m0 = blockIdx.y * 64;
    const int n0 = blockIdx.x * 64;
    const int tid = threadIdx.x;
    const int tx = tid & 15, ty = tid >> 4;

    float acc[4][4];
#pragma unroll
    for (int i = 0; i < 4; i++)
#pragma unroll
        for (int j = 0; j < 4; j++) acc[i][j] = 0.f;

    for (int k0 = 0; k0 < K; k0 += 32) {
#pragma unroll
        for (int t = tid; t < 64 * 8; t += 256) {
            int row = t >> 3, c4 = t & 7;
            float4 v = *(const float4*)&X[(size_t)(m0 + row) * K + k0 + c4 * 4];
            As[c4*4+0][row] = v.x; As[c4*4+1][row] = v.y;
            As[c4*4+2][row] = v.z; As[c4*4+3][row] = v.w;
        }
#pragma unroll
        for (int t = tid; t < 64 * 8; t += 256) {
            int row = t >> 3, c4 = t & 7;
            float4 v = *(const float4*)&W[(size_t)(n0 + row) * K + k0 + c4 * 4];
            Bs[c4*4+0][row] = v.x; Bs[c4*4+1][row] = v.y;
            Bs[c4*4+2][row] = v.z; Bs[c4*4+3][row] = v.w;
        }
        __syncthreads();
#pragma unroll
        for (int kk = 0; kk < 32; kk++) {
            float4 a = *(const float4*)&As[kk][ty * 4];
            float4 b = *(const float4*)&Bs[kk][tx * 4];
            float av[4] = {a.x, a.y, a.z, a.w};
            float bv[4] = {b.x, b.y, b.z, b.w};
#pragma unroll
            for (int i = 0; i < 4; i++)
#pragma unroll
                for (int j = 0; j < 4; j++) acc[i][j] += av[i] * bv[j];
        }
        __syncthreads();
    }

#pragma unroll
    for (int i = 0; i < 4; i++) {
        int m = m0 + ty * 4 + i;
#pragma unroll
        for (int j = 0; j < 4; j++) {
            int n = n0 + tx * 4 + j;
            if (mode == 0) {
                int b = m >> 11, s = m & 2047;
                int h = n >> 6, dk = n & 63;
                out[(((size_t)(b * Hh + h) * Ss) + s) * DKk + dk] = acc[i][j];
            } else {
                out[(size_t)m * Dd + n] = acc[i][j];
            }
        }
    }
}

// ---------------------------------------------------------------------------
// Scores GEMM (NT, K=64 single pass): C[i,j] = 0.125 * dot(Q_i, K_j)
// Per (b,h): 2048x2048. Tile 64x64. Writes raw (pre-softmax) scores.
// ---------------------------------------------------------------------------
__global__ __launch_bounds__(256) void scores_kernel(
    const float* __restrict__ Q, const float* __restrict__ Kt,
    float* __restrict__ P)
{
    __shared__ float As[64][68];
    __shared__ float Bs[64][68];
    const int bh = blockIdx.z;
    const float* Qb = Q + (size_t)bh * Ss * DKk;
    const float* Kb = Kt + (size_t)bh * Ss * DKk;
    float* Pb = P + (size_t)bh * Ss * Ss;

    const int m0 = blockIdx.y * 64;
    const int n0 = blockIdx.x * 64;
    const int tid = threadIdx.x;
    const int tx = tid & 15, ty = tid >> 4;

    float acc[4][4];
#pragma unroll
    for (int i = 0; i < 4; i++)
#pragma unroll
        for (int j = 0; j < 4; j++) acc[i][j] = 0.f;

#pragma unroll
    for (int t = tid; t < 64 * 16; t += 256) {
        int row = t >> 4, c4 = t & 15;
        float4 v = *(const float4*)&Qb[(size_t)(m0 + row) * DKk + c4 * 4];
        As[c4*4+0][row] = v.x; As[c4*4+1][row] = v.y;
        As[c4*4+2][row] = v.z; As[c4*4+3][row] = v.w;
    }
#pragma unroll
    for (int t = tid; t < 64 * 16; t += 256) {
        int row = t >> 4, c4 = t & 15;
        float4 v = *(const float4*)&Kb[(size_t)(n0 + row) * DKk + c4 * 4];
        Bs[c4*4+0][row] = v.x; Bs[c4*4+1][row] = v.y;
        Bs[c4*4+2][row] = v.z; Bs[c4*4+3][row] = v.w;
    }
    __syncthreads();
#pragma unroll
    for (int kk = 0; kk < 64; kk++) {
        float4 a = *(const float4*)&As[kk][ty * 4];
        float4 b = *(const float4*)&Bs[kk][tx * 4];
        float av[4] = {a.x, a.y, a.z, a.w};
        float bv[4] = {b.x, b.y, b.z, b.w};
#pragma unroll
        for (int i = 0; i < 4; i++)
#pragma unroll
            for (int j = 0; j < 4; j++) acc[i][j] += av[i] * bv[j];
    }

#pragma unroll
    for (int i = 0; i < 4; i++) {
        int m = m0 + ty * 4 + i;
#pragma unroll
        for (int j = 0; j < 4; j += 4) {
            int n = n0 + tx * 4;
            float4 o;
            o.x = acc[i][0] * SCALE; o.y = acc[i][1] * SCALE;
            o.z = acc[i][2] * SCALE; o.w = acc[i][3] * SCALE;
            *(float4*)&Pb[(size_t)m * Ss + n] = o;
        }
    }
}

// ---------------------------------------------------------------------------
// Row softmax in place over p_attn. One block (256 thr) per row of 2048.
// ---------------------------------------------------------------------------
__global__ __launch_bounds__(256) void softmax_kernel(float* __restrict__ P)
{
    const size_t row = blockIdx.x;
    float* p = P + row * (size_t)Ss;
    const int tid = threadIdx.x;

    float4 v0 = ((const float4*)p)[tid * 2 + 0];
    float4 v1 = ((const float4*)p)[tid * 2 + 1];

    __shared__ float red[256];
    float m = fmaxf(fmaxf(fmaxf(v0.x, v0.y), fmaxf(v0.z, v0.w)),
                    fmaxf(fmaxf(v1.x, v1.y), fmaxf(v1.z, v1.w)));
    red[tid] = m; __syncthreads();
#pragma unroll
    for (int s = 128; s > 0; s >>= 1) {
        if (tid < s) red[tid] = fmaxf(red[tid], red[tid + s]);
        __syncthreads();
    }
    const float mx = red[0];
    __syncthreads();

    v0.x = __expf(v0.x - mx); v0.y = __expf(v0.y - mx);
    v0.z = __expf(v0.z - mx); v0.w = __expf(v0.w - mx);
    v1.x = __expf(v1.x - mx); v1.y = __expf(v1.y - mx);
    v1.z = __expf(v1.z - mx); v1.w = __expf(v1.w - mx);

    float s8 = (v0.x + v0.y + v0.z + v0.w) + (v1.x + v1.y + v1.z + v1.w);
    red[tid] = s8; __syncthreads();
#pragma unroll
    for (int s = 128; s > 0; s >>= 1) {
        if (tid < s) red[tid] += red[tid + s];
        __syncthreads();
    }
    const float inv = 1.f / red[0];

    v0.x *= inv; v0.y *= inv; v0.z *= inv; v0.w *= inv;
    v1.x *= inv; v1.y *= inv; v1.z *= inv; v1.w *= inv;
    ((float4*)p)[tid * 2 + 0] = v0;
    ((float4*)p)[tid * 2 + 1] = v1;
}

// ---------------------------------------------------------------------------
// PV GEMM (NN): O[i,n] = sum_j P[i,j] * V[j,n], per (b,h): 2048x64, K=2048.
// Tile 64(rows) x 64(full N), KT=32. Writes merged-head layout [b,s,d].
// ---------------------------------------------------------------------------
__global__ __launch_bounds__(256) void pv_kernel(
    const float* __restrict__ P, const float* __restrict__ V,
    float* __restrict__ O)
{
    __shared__ float Ps[32][68];
    __shared__ float Vs[32][68];
    const int bh = blockIdx.z;
    const int b = bh >> 3, h = bh & 7;
    const float* Pb = P + (size_t)bh * Ss * Ss;
    const float* Vb = V + (size_t)bh * Ss * DKk;

    const int m0 = blockIdx.y * 64;
    const int tid = threadIdx.x;
    const int tx = tid & 15, ty = tid >> 4;

    float acc[4][4];
#pragma unroll
    for (int i = 0; i < 4; i++)
#pragma unroll
        for (int j = 0; j < 4; j++) acc[i][j] = 0.f;

    for (int j0 = 0; j0 < Ss; j0 += 32) {
#pragma unroll
        for (int t = tid; t < 64 * 8; t += 256) {
            int row = t >> 3, c4 = t & 7;   // row = output row i, c4 over j
            float4 v = *(const float4*)&Pb[(size_t)(m0 + row) * Ss + j0 + c4 * 4];
            Ps[c4*4+0][row] = v.x; Ps[c4*4+1][row] = v.y;
            Ps[c4*4+2][row] = v.z; Ps[c4*4+3][row] = v.w;
        }
#pragma unroll
        for (int t = tid; t < 32 * 16; t += 256) {
            int row = t >> 4, c4 = t & 15;  // row over j, c4 over n
            float4 v = *(const float4*)&Vb[(size_t)(j0 + row) * DKk + c4 * 4];
            *(float4*)&Vs[row][c4 * 4] = v;
        }
        __syncthreads();
#pragma unroll
        for (int kk = 0; kk < 32; kk++) {
            float4 a = *(const float4*)&Ps[kk][ty * 4];
            float4 bvv = *(const float4*)&Vs[kk][tx * 4];
            float av[4] = {a.x, a.y, a.z, a.w};
            float bv[4] = {bvv.x, bvv.y, bvv.z, bvv.w};
#pragma unroll
            for (int i = 0; i < 4; i++)
#pragma unroll
                for (int j = 0; j < 4; j++) acc[i][j] += av[i] * bv[j];
        }
        __syncthreads();
    }

#pragma unroll
    for (int i = 0; i < 4; i++) {
        int s = m0 + ty * 4 + i;
        int n = tx * 4;
        float4 o;
        o.x = acc[i][0]; o.y = acc[i][1]; o.z = acc[i][2]; o.w = acc[i][3];
        *(float4*)&O[((size_t)(b * Ss + s) * Dd) + h * DKk + n] = o;
    }
}

// ---------------------------------------------------------------------------
extern "C" void kernel_launch(void* const* d_in, const int* in_sizes, int n_in,
                              void* d_out, int out_size)
{
    const float* query = (const float*)d_in[0];
    const float* key   = (const float*)d_in[1];
    const float* value = (const float*)d_in[2];
    const float* w_q   = (const float*)d_in[3];
    const float* w_k   = (const float*)d_in[4];
    const float* w_v   = (const float*)d_in[5];
    const float* w_o   = (const float*)d_in[6];

    float* out_main = (float*)d_out;                          // [B,S,D]
    float* p_attn   = out_main + (size_t)MM * Dd;             // [B,H,S,S]

    float *Qp, *Kp, *Vp, *Op;
    cudaGetSymbolAddress((void**)&Qp, g_Q);
    cudaGetSymbolAddress((void**)&Kp, g_K);
    cudaGetSymbolAddress((void**)&Vp, g_V);
    cudaGetSymbolAddress((void**)&Op, g_O);

    dim3 pj_grid(Dd / 64, MM / 64);     // (8, 64)
    proj_kernel<<<pj_grid, 256>>>(query, w_q, Qp, Dd, 0);
    proj_kernel<<<pj_grid, 256>>>(key,   w_k, Kp, Dd, 0);
    proj_kernel<<<pj_grid, 256>>>(value, w_v, Vp, Dd, 0);

    dim3 sc_grid(Ss / 64, Ss / 64, BH); // (32, 32, 16)
    scores_kernel<<<sc_grid, 256>>>(Qp, Kp, p_attn);

    softmax_kernel<<<BH * Ss, 256>>>(p_attn);

    dim3 pv_grid(1, Ss / 64, BH);       // (1, 32, 16)
    pv_kernel<<<pv_grid, 256>>>(p_attn, Vp, Op);

    proj_kernel<<<pj_grid, 256>>>(Op, w_o, out_main, Dd, 1);
}

// round 3
// speedup vs baseline: 3.4346x; 3.4346x over previous
#include <cuda_runtime.h>
#include <cuda_bf16.h>
#include <cstdint>
#include <cstddef>

#define Ss 2048
#define Dd 512
#define Hh 8
#define DKk 64
#define BH 16
#define MM 4096
#define SCALE 0.125f

// Scratch (no allocation allowed)
__device__ float g_Q[BH * Ss * DKk];    // [b,h,s,dk]
__device__ float g_K[BH * Ss * DKk];    // [b,h,s,dk]
__device__ float g_Vt[BH * DKk * Ss];   // [b,h,dk,s]
__device__ float g_O[MM * Dd];          // merged heads [b,s,d]

// Pack two floats into a bf16x2 register (lo half = first element)
__device__ __forceinline__ uint32_t pack_bf2(__nv_bfloat16 a, __nv_bfloat16 b) {
    __nv_bfloat162 t;
    t.x = a; t.y = b;
    return *reinterpret_cast<uint32_t*>(&t);
}

__device__ __forceinline__ void mma_bf16(float& c0, float& c1, float& c2, float& c3,
                                         uint32_t a0, uint32_t a1, uint32_t a2, uint32_t a3,
                                         uint32_t b0, uint32_t b1) {
    asm volatile(
        "mma.sync.aligned.m16n8k16.row.col.f32.bf16.bf16.f32 "
        "{%0,%1,%2,%3}, {%4,%5,%6,%7}, {%8,%9}, {%0,%1,%2,%3};"
        : "+f"(c0), "+f"(c1), "+f"(c2), "+f"(c3)
        : "r"(a0), "r"(a1), "r"(a2), "r"(a3), "r"(b0), "r"(b1));
}

// Modes: 0 = proj->head-split [b,h,s,dk]; 1 = proj->Vt [b,h,dk,s]; 2 = proj plain [m,Dd];
//        3 = scores (per-bh, *SCALE); 4 = PV (per-bh, merged-head out)
// C[m,n] = sum_k A[m,k] * B[n,k]   (NT, k-contiguous both sides)
template <int MODE>
__global__ __launch_bounds__(256) void mma_gemm(
    const float* __restrict__ A, const float* __restrict__ B,
    float* __restrict__ C, int K, int lda, int ldb)
{
    // Per-bh pointer offsets
    int b_ = 0, h_ = 0;
    if (MODE == 3) {
        const int bh = blockIdx.z;
        A += (size_t)bh * Ss * DKk;
        B += (size_t)bh * Ss * DKk;
        C += (size_t)bh * Ss * Ss;
    } else if (MODE == 4) {
        const int bh = blockIdx.z;
        b_ = bh >> 3; h_ = bh & 7;
        A += (size_t)bh * Ss * Ss;
        B += (size_t)bh * DKk * Ss;
    }

    const int m0 = blockIdx.y * 128;
    const int n0 = blockIdx.x * 64;
    const int tid = threadIdx.x;
    const int lane = tid & 31, wid = tid >> 5;
    const int warp_m = wid & 3, warp_n = wid >> 2;     // 4 x 2 warps
    const int g = lane >> 2, tk = lane & 3;

    // 40 bf16 per row = 20 words (conflict-free for the fragment access pattern)
    __shared__ uint32_t AsHi[128 * 20], AsLo[128 * 20];
    __shared__ uint32_t BsHi[64 * 20],  BsLo[64 * 20];

    float acc[2][4][4];
#pragma unroll
    for (int t = 0; t < 2; t++)
#pragma unroll
        for (int u = 0; u < 4; u++)
#pragma unroll
            for (int j = 0; j < 4; j++) acc[t][u][j] = 0.f;

    const int NC = K >> 5;   // K / 32
    float4 pa[4], pb[2];

    // prefetch chunk 0
#pragma unroll
    for (int i = 0; i < 4; i++) {
        int v = tid + 256 * i, row = v >> 3, c4 = v & 7;
        pa[i] = *(const float4*)&A[(size_t)(m0 + row) * lda + c4 * 4];
    }
#pragma unroll
    for (int i = 0; i < 2; i++) {
        int v = tid + 256 * i, row = v >> 3, c4 = v & 7;
        pb[i] = *(const float4*)&B[(size_t)(n0 + row) * ldb + c4 * 4];
    }

    for (int c = 0; c < NC; c++) {
        // store current chunk to smem (convert to bf16 hi/lo)
#pragma unroll
        for (int i = 0; i < 4; i++) {
            int v = tid + 256 * i, row = v >> 3, c4 = v & 7;
            float f[4] = {pa[i].x, pa[i].y, pa[i].z, pa[i].w};
            int w = row * 20 + c4 * 2;
#pragma unroll
            for (int j = 0; j < 2; j++) {
                __nv_bfloat16 ha = __float2bfloat16(f[2 * j]);
                __nv_bfloat16 hb = __float2bfloat16(f[2 * j + 1]);
                float la = f[2 * j] - __bfloat162float(ha);
                float lb = f[2 * j + 1] - __bfloat162float(hb);
                AsHi[w + j] = pack_bf2(ha, hb);
                AsLo[w + j] = pack_bf2(__float2bfloat16(la), __float2bfloat16(lb));
            }
        }
#pragma unroll
        for (int i = 0; i < 2; i++) {
            int v = tid + 256 * i, row = v >> 3, c4 = v & 7;
            float f[4] = {pb[i].x, pb[i].y, pb[i].z, pb[i].w};
            int w = row * 20 + c4 * 2;
#pragma unroll
            for (int j = 0; j < 2; j++) {
                __nv_bfloat16 ha = __float2bfloat16(f[2 * j]);
                __nv_bfloat16 hb = __float2bfloat16(f[2 * j + 1]);
                float la = f[2 * j] - __bfloat162float(ha);
                float lb = f[2 * j + 1] - __bfloat162float(hb);
                BsHi[w + j] = pack_bf2(ha, hb);
                BsLo[w + j] = pack_bf2(__float2bfloat16(la), __float2bfloat16(lb));
            }
        }
        __syncthreads();

        // prefetch next chunk
        if (c + 1 < NC) {
            int k0 = (c + 1) * 32;
#pragma unroll
            for (int i = 0; i < 4; i++) {
                int v = tid + 256 * i, row = v >> 3, c4 = v & 7;
                pa[i] = *(const float4*)&A[(size_t)(m0 + row) * lda + k0 + c4 * 4];
            }
#pragma unroll
            for (int i = 0; i < 2; i++) {
                int v = tid + 256 * i, row = v >> 3, c4 = v & 7;
                pb[i] = *(const float4*)&B[(size_t)(n0 + row) * ldb + k0 + c4 * 4];
            }
        }

        // compute: 2 k16 steps
#pragma unroll
        for (int s = 0; s < 2; s++) {
            const int s8 = s * 8;
            uint32_t ah[2][4], al[2][4];
#pragma unroll
            for (int t = 0; t < 2; t++) {
                int r = (warp_m * 32 + t * 16 + g) * 20 + s8 + tk;
                ah[t][0] = AsHi[r];            al[t][0] = AsLo[r];
                ah[t][1] = AsHi[r + 8 * 20];   al[t][1] = AsLo[r + 8 * 20];
                ah[t][2] = AsHi[r + 4];        al[t][2] = AsLo[r + 4];
                ah[t][3] = AsHi[r + 8 * 20 + 4]; al[t][3] = AsLo[r + 8 * 20 + 4];
            }
            uint32_t bh2[4][2], bl2[4][2];
#pragma unroll
            for (int u = 0; u < 4; u++) {
                int r = (warp_n * 32 + u * 8 + g) * 20 + s8 + tk;
                bh2[u][0] = BsHi[r];     bl2[u][0] = BsLo[r];
                bh2[u][1] = BsHi[r + 4]; bl2[u][1] = BsLo[r + 4];
            }
#pragma unroll
            for (int t = 0; t < 2; t++)
#pragma unroll
                for (int u = 0; u < 4; u++) {
                    float* cc = acc[t][u];
                    mma_bf16(cc[0], cc[1], cc[2], cc[3],
                             ah[t][0], ah[t][1], ah[t][2], ah[t][3], bh2[u][0], bh2[u][1]);
                    mma_bf16(cc[0], cc[1], cc[2], cc[3],
                             ah[t][0], ah[t][1], ah[t][2], ah[t][3], bl2[u][0], bl2[u][1]);
                    mma_bf16(cc[0], cc[1], cc[2], cc[3],
                             al[t][0], al[t][1], al[t][2], al[t][3], bh2[u][0], bh2[u][1]);
                }
        }
        __syncthreads();
    }

    // ---------------- epilogue ----------------
#pragma unroll
    for (int t = 0; t < 2; t++) {
#pragma unroll
        for (int half = 0; half < 2; half++) {
            const int m = m0 + warp_m * 32 + t * 16 + g + half * 8;
#pragma unroll
            for (int u = 0; u < 4; u++) {
                const int n = n0 + warp_n * 32 + u * 8 + tk * 2;
                float v0 = acc[t][u][half * 2 + 0];
                float v1 = acc[t][u][half * 2 + 1];
                if (MODE == 0) {
                    int b = m >> 11, s = m & 2047;
                    int h = n >> 6, dk = n & 63;
                    float2 o = make_float2(v0, v1);
                    *(float2*)&C[(((size_t)(b * Hh + h) * Ss + s) * DKk) + dk] = o;
                } else if (MODE == 1) {
                    int b = m >> 11, s = m & 2047;
                    int h = n >> 6, dk = n & 63;
                    C[(((size_t)(b * Hh + h) * DKk + dk) * Ss) + s] = v0;
                    C[(((size_t)(b * Hh + h) * DKk + dk + 1) * Ss) + s] = v1;
                } else if (MODE == 2) {
                    *(float2*)&C[(size_t)m * Dd + n] = make_float2(v0, v1);
                } else if (MODE == 3) {
                    *(float2*)&C[(size_t)m * Ss + n] = make_float2(v0 * SCALE, v1 * SCALE);
                } else {  // MODE 4
                    *(float2*)&C[((size_t)(b_ * Ss + m)) * Dd + h_ * DKk + n] =
                        make_float2(v0, v1);
                }
            }
        }
    }
}

// ===================== Softmax (rows of 2048, in place) =====================
__global__ __launch_bounds__(256) void softmax_kernel(float* __restrict__ P)
{
    const size_t row = blockIdx.x;
    float* p = P + row * (size_t)Ss;
    const int tid = threadIdx.x;

    float4 v0 = ((const float4*)p)[tid * 2 + 0];
    float4 v1 = ((const float4*)p)[tid * 2 + 1];

    __shared__ float red[256];
    float m = fmaxf(fmaxf(fmaxf(v0.x, v0.y), fmaxf(v0.z, v0.w)),
                    fmaxf(fmaxf(v1.x, v1.y), fmaxf(v1.z, v1.w)));
    red[tid] = m; __syncthreads();
#pragma unroll
    for (int s = 128; s > 0; s >>= 1) {
        if (tid < s) red[tid] = fmaxf(red[tid], red[tid + s]);
        __syncthreads();
    }
    const float mx = red[0];
    __syncthreads();

    v0.x = __expf(v0.x - mx); v0.y = __expf(v0.y - mx);
    v0.z = __expf(v0.z - mx); v0.w = __expf(v0.w - mx);
    v1.x = __expf(v1.x - mx); v1.y = __expf(v1.y - mx);
    v1.z = __expf(v1.z - mx); v1.w = __expf(v1.w - mx);

    float s8 = (v0.x + v0.y + v0.z + v0.w) + (v1.x + v1.y + v1.z + v1.w);
    red[tid] = s8; __syncthreads();
#pragma unroll
    for (int s = 128; s > 0; s >>= 1) {
        if (tid < s) red[tid] += red[tid + s];
        __syncthreads();
    }
    const float inv = 1.f / red[0];

    v0.x *= inv; v0.y *= inv; v0.z *= inv; v0.w *= inv;
    v1.x *= inv; v1.y *= inv; v1.z *= inv; v1.w *= inv;
    ((float4*)p)[tid * 2 + 0] = v0;
    ((float4*)p)[tid * 2 + 1] = v1;
}

// ===================== Launch =====================
extern "C" void kernel_launch(void* const* d_in, const int* in_sizes, int n_in,
                              void* d_out, int out_size)
{
    const float* query = (const float*)d_in[0];
    const float* key   = (const float*)d_in[1];
    const float* value = (const float*)d_in[2];
    const float* w_q   = (const float*)d_in[3];
    const float* w_k   = (const float*)d_in[4];
    const float* w_v   = (const float*)d_in[5];
    const float* w_o   = (const float*)d_in[6];

    float* out_main = (float*)d_out;
    float* p_attn   = out_main + (size_t)MM * Dd;

    float *Qp, *Kp, *Vp, *Op;
    cudaGetSymbolAddress((void**)&Qp, g_Q);
    cudaGetSymbolAddress((void**)&Kp, g_K);
    cudaGetSymbolAddress((void**)&Vp, g_Vt);
    cudaGetSymbolAddress((void**)&Op, g_O);

    dim3 pj_grid(Dd / 64, MM / 128);          // (8, 32)
    mma_gemm<0><<<pj_grid, 256>>>(query, w_q, Qp, Dd, Dd, Dd);
    mma_gemm<0><<<pj_grid, 256>>>(key,   w_k, Kp, Dd, Dd, Dd);
    mma_gemm<1><<<pj_grid, 256>>>(value, w_v, Vp, Dd, Dd, Dd);

    dim3 sc_grid(Ss / 64, Ss / 128, BH);      // (32, 16, 16)
    mma_gemm<3><<<sc_grid, 256>>>(Qp, Kp, p_attn, DKk, DKk, DKk);

    softmax_kernel<<<BH * Ss, 256>>>(p_attn);

    dim3 pv_grid(DKk / 64, Ss / 128, BH);     // (1, 16, 16)
    mma_gemm<4><<<pv_grid, 256>>>(p_attn, Vp, Op, Ss, Ss, Ss);

    mma_gemm<2><<<pj_grid, 256>>>(Op, w_o, out_main, Dd, Dd, Dd);
}

// round 4
// speedup vs baseline: 3.8240x; 1.1134x over previous
#include <cuda_runtime.h>
#include <cuda_bf16.h>
#include <cstdint>
#include <cstddef>

#define Ss 2048
#define Dd 512
#define Hh 8
#define DKk 64
#define BH 16
#define MM 4096
#define SCALE 0.125f

// Scratch (no allocation allowed)
__device__ float g_Q[BH * Ss * DKk];      // [b,h,s,dk]
__device__ float g_K[BH * Ss * DKk];      // [b,h,s,dk]
__device__ float g_Vt[BH * DKk * Ss];     // [b,h,dk,s]
__device__ float g_O[MM * Dd];            // merged heads [b,s,d]
__device__ float g_lpart[BH * Ss * 64];   // per-row partial expsums (64 slots)
__device__ float g_invl[BH * Ss];         // 1 / rowsum

__device__ __forceinline__ uint32_t pack_bf2(__nv_bfloat16 a, __nv_bfloat16 b) {
    __nv_bfloat162 t;
    t.x = a; t.y = b;
    return *reinterpret_cast<uint32_t*>(&t);
}

__device__ __forceinline__ void hilo(float f0, float f1, uint32_t& hi, uint32_t& lo) {
    __nv_bfloat16 ha = __float2bfloat16(f0);
    __nv_bfloat16 hb = __float2bfloat16(f1);
    hi = pack_bf2(ha, hb);
    lo = pack_bf2(__float2bfloat16(f0 - __bfloat162float(ha)),
                  __float2bfloat16(f1 - __bfloat162float(hb)));
}

__device__ __forceinline__ void mma_bf16(float& c0, float& c1, float& c2, float& c3,
                                         uint32_t a0, uint32_t a1, uint32_t a2, uint32_t a3,
                                         uint32_t b0, uint32_t b1) {
    asm volatile(
        "mma.sync.aligned.m16n8k16.row.col.f32.bf16.bf16.f32 "
        "{%0,%1,%2,%3}, {%4,%5,%6,%7}, {%8,%9}, {%0,%1,%2,%3};"
        : "+f"(c0), "+f"(c1), "+f"(c2), "+f"(c3)
        : "r"(a0), "r"(a1), "r"(a2), "r"(a3), "r"(b0), "r"(b1));
}

// ================= Projection GEMM (NT): C[m,n] = sum_k A[m,k] B[n,k] =================
// Modes: 0 = head-split [b,h,s,dk]; 1 = Vt [b,h,dk,s]; 2 = plain [m,Dd]
template <int MODE>
__global__ __launch_bounds__(256) void mma_gemm(
    const float* __restrict__ A, const float* __restrict__ B,
    float* __restrict__ C, int K, int lda, int ldb)
{
    const int m0 = blockIdx.y * 128;
    const int n0 = blockIdx.x * 64;
    const int tid = threadIdx.x;
    const int lane = tid & 31, wid = tid >> 5;
    const int warp_m = wid & 3, warp_n = wid >> 2;
    const int g = lane >> 2, tk = lane & 3;

    __shared__ uint32_t AsHi[128 * 20], AsLo[128 * 20];
    __shared__ uint32_t BsHi[64 * 20],  BsLo[64 * 20];

    float acc[2][4][4];
#pragma unroll
    for (int t = 0; t < 2; t++)
#pragma unroll
        for (int u = 0; u < 4; u++)
#pragma unroll
            for (int j = 0; j < 4; j++) acc[t][u][j] = 0.f;

    const int NC = K >> 5;
    float4 pa[4], pb[2];

#pragma unroll
    for (int i = 0; i < 4; i++) {
        int v = tid + 256 * i, row = v >> 3, c4 = v & 7;
        pa[i] = *(const float4*)&A[(size_t)(m0 + row) * lda + c4 * 4];
    }
#pragma unroll
    for (int i = 0; i < 2; i++) {
        int v = tid + 256 * i, row = v >> 3, c4 = v & 7;
        pb[i] = *(const float4*)&B[(size_t)(n0 + row) * ldb + c4 * 4];
    }

    for (int c = 0; c < NC; c++) {
#pragma unroll
        for (int i = 0; i < 4; i++) {
            int v = tid + 256 * i, row = v >> 3, c4 = v & 7;
            float f[4] = {pa[i].x, pa[i].y, pa[i].z, pa[i].w};
            int w = row * 20 + c4 * 2;
            hilo(f[0], f[1], AsHi[w], AsLo[w]);
            hilo(f[2], f[3], AsHi[w + 1], AsLo[w + 1]);
        }
#pragma unroll
        for (int i = 0; i < 2; i++) {
            int v = tid + 256 * i, row = v >> 3, c4 = v & 7;
            float f[4] = {pb[i].x, pb[i].y, pb[i].z, pb[i].w};
            int w = row * 20 + c4 * 2;
            hilo(f[0], f[1], BsHi[w], BsLo[w]);
            hilo(f[2], f[3], BsHi[w + 1], BsLo[w + 1]);
        }
        __syncthreads();

        if (c + 1 < NC) {
            int k0 = (c + 1) * 32;
#pragma unroll
            for (int i = 0; i < 4; i++) {
                int v = tid + 256 * i, row = v >> 3, c4 = v & 7;
                pa[i] = *(const float4*)&A[(size_t)(m0 + row) * lda + k0 + c4 * 4];
            }
#pragma unroll
            for (int i = 0; i < 2; i++) {
                int v = tid + 256 * i, row = v >> 3, c4 = v & 7;
                pb[i] = *(const float4*)&B[(size_t)(n0 + row) * ldb + k0 + c4 * 4];
            }
        }

#pragma unroll
        for (int s = 0; s < 2; s++) {
            const int s8 = s * 8;
            uint32_t ah[2][4], al[2][4];
#pragma unroll
            for (int t = 0; t < 2; t++) {
                int r = (warp_m * 32 + t * 16 + g) * 20 + s8 + tk;
                ah[t][0] = AsHi[r];              al[t][0] = AsLo[r];
                ah[t][1] = AsHi[r + 8 * 20];     al[t][1] = AsLo[r + 8 * 20];
                ah[t][2] = AsHi[r + 4];          al[t][2] = AsLo[r + 4];
                ah[t][3] = AsHi[r + 8 * 20 + 4]; al[t][3] = AsLo[r + 8 * 20 + 4];
            }
            uint32_t bh2[4][2], bl2[4][2];
#pragma unroll
            for (int u = 0; u < 4; u++) {
                int r = (warp_n * 32 + u * 8 + g) * 20 + s8 + tk;
                bh2[u][0] = BsHi[r];     bl2[u][0] = BsLo[r];
                bh2[u][1] = BsHi[r + 4]; bl2[u][1] = BsLo[r + 4];
            }
#pragma unroll
            for (int t = 0; t < 2; t++)
#pragma unroll
                for (int u = 0; u < 4; u++) {
                    float* cc = acc[t][u];
                    mma_bf16(cc[0], cc[1], cc[2], cc[3],
                             ah[t][0], ah[t][1], ah[t][2], ah[t][3], bh2[u][0], bh2[u][1]);
                    mma_bf16(cc[0], cc[1], cc[2], cc[3],
                             ah[t][0], ah[t][1], ah[t][2], ah[t][3], bl2[u][0], bl2[u][1]);
                    mma_bf16(cc[0], cc[1], cc[2], cc[3],
                             al[t][0], al[t][1], al[t][2], al[t][3], bh2[u][0], bh2[u][1]);
                }
        }
        __syncthreads();
    }

#pragma unroll
    for (int t = 0; t < 2; t++) {
#pragma unroll
        for (int half = 0; half < 2; half++) {
            const int m = m0 + warp_m * 32 + t * 16 + g + half * 8;
#pragma unroll
            for (int u = 0; u < 4; u++) {
                const int n = n0 + warp_n * 32 + u * 8 + tk * 2;
                float v0 = acc[t][u][half * 2 + 0];
                float v1 = acc[t][u][half * 2 + 1];
                if (MODE == 0) {
                    int b = m >> 11, s = m & 2047;
                    int h = n >> 6, dk = n & 63;
                    *(float2*)&C[(((size_t)(b * Hh + h) * Ss + s) * DKk) + dk] = make_float2(v0, v1);
                } else if (MODE == 1) {
                    int b = m >> 11, s = m & 2047;
                    int h = n >> 6, dk = n & 63;
                    C[(((size_t)(b * Hh + h) * DKk + dk) * Ss) + s] = v0;
                    C[(((size_t)(b * Hh + h) * DKk + dk + 1) * Ss) + s] = v1;
                } else {
                    *(float2*)&C[(size_t)m * Dd + n] = make_float2(v0, v1);
                }
            }
        }
    }
}

// ================ Scores + exp: P~ = exp(QK^T/8), partial rowsums ================
__global__ __launch_bounds__(256) void scores_exp_kernel(
    const float* __restrict__ Q, const float* __restrict__ Kt,
    float* __restrict__ P, float* __restrict__ lpart)
{
    const int bh = blockIdx.z;
    Q += (size_t)bh * Ss * DKk;
    Kt += (size_t)bh * Ss * DKk;
    P += (size_t)bh * Ss * Ss;

    const int m0 = blockIdx.y * 128;
    const int n0 = blockIdx.x * 64;
    const int tid = threadIdx.x;
    const int lane = tid & 31, wid = tid >> 5;
    const int warp_m = wid & 3, warp_n = wid >> 2;
    const int g = lane >> 2, tk = lane & 3;

    __shared__ uint32_t AsHi[128 * 20], AsLo[128 * 20];
    __shared__ uint32_t BsHi[64 * 20],  BsLo[64 * 20];

    float acc[2][4][4];
#pragma unroll
    for (int t = 0; t < 2; t++)
#pragma unroll
        for (int u = 0; u < 4; u++)
#pragma unroll
            for (int j = 0; j < 4; j++) acc[t][u][j] = 0.f;

    float4 pa[4], pb[2];
#pragma unroll
    for (int i = 0; i < 4; i++) {
        int v = tid + 256 * i, row = v >> 3, c4 = v & 7;
        pa[i] = *(const float4*)&Q[(size_t)(m0 + row) * DKk + c4 * 4];
    }
#pragma unroll
    for (int i = 0; i < 2; i++) {
        int v = tid + 256 * i, row = v >> 3, c4 = v & 7;
        pb[i] = *(const float4*)&Kt[(size_t)(n0 + row) * DKk + c4 * 4];
    }

    for (int c = 0; c < 2; c++) {
#pragma unroll
        for (int i = 0; i < 4; i++) {
            int v = tid + 256 * i, row = v >> 3, c4 = v & 7;
            float f[4] = {pa[i].x, pa[i].y, pa[i].z, pa[i].w};
            int w = row * 20 + c4 * 2;
            hilo(f[0], f[1], AsHi[w], AsLo[w]);
            hilo(f[2], f[3], AsHi[w + 1], AsLo[w + 1]);
        }
#pragma unroll
        for (int i = 0; i < 2; i++) {
            int v = tid + 256 * i, row = v >> 3, c4 = v & 7;
            float f[4] = {pb[i].x, pb[i].y, pb[i].z, pb[i].w};
            int w = row * 20 + c4 * 2;
            hilo(f[0], f[1], BsHi[w], BsLo[w]);
            hilo(f[2], f[3], BsHi[w + 1], BsLo[w + 1]);
        }
        __syncthreads();

        if (c == 0) {
#pragma unroll
            for (int i = 0; i < 4; i++) {
                int v = tid + 256 * i, row = v >> 3, c4 = v & 7;
                pa[i] = *(const float4*)&Q[(size_t)(m0 + row) * DKk + 32 + c4 * 4];
            }
#pragma unroll
            for (int i = 0; i < 2; i++) {
                int v = tid + 256 * i, row = v >> 3, c4 = v & 7;
                pb[i] = *(const float4*)&Kt[(size_t)(n0 + row) * DKk + 32 + c4 * 4];
            }
        }

#pragma unroll
        for (int s = 0; s < 2; s++) {
            const int s8 = s * 8;
            uint32_t ah[2][4], al[2][4];
#pragma unroll
            for (int t = 0; t < 2; t++) {
                int r = (warp_m * 32 + t * 16 + g) * 20 + s8 + tk;
                ah[t][0] = AsHi[r];              al[t][0] = AsLo[r];
                ah[t][1] = AsHi[r + 8 * 20];     al[t][1] = AsLo[r + 8 * 20];
                ah[t][2] = AsHi[r + 4];          al[t][2] = AsLo[r + 4];
                ah[t][3] = AsHi[r + 8 * 20 + 4]; al[t][3] = AsLo[r + 8 * 20 + 4];
            }
            uint32_t bh2[4][2], bl2[4][2];
#pragma unroll
            for (int u = 0; u < 4; u++) {
                int r = (warp_n * 32 + u * 8 + g) * 20 + s8 + tk;
                bh2[u][0] = BsHi[r];     bl2[u][0] = BsLo[r];
                bh2[u][1] = BsHi[r + 4]; bl2[u][1] = BsLo[r + 4];
            }
#pragma unroll
            for (int t = 0; t < 2; t++)
#pragma unroll
                for (int u = 0; u < 4; u++) {
                    float* cc = acc[t][u];
                    mma_bf16(cc[0], cc[1], cc[2], cc[3],
                             ah[t][0], ah[t][1], ah[t][2], ah[t][3], bh2[u][0], bh2[u][1]);
                    mma_bf16(cc[0], cc[1], cc[2], cc[3],
                             ah[t][0], ah[t][1], ah[t][2], ah[t][3], bl2[u][0], bl2[u][1]);
                    mma_bf16(cc[0], cc[1], cc[2], cc[3],
                             al[t][0], al[t][1], al[t][2], al[t][3], bh2[u][0], bh2[u][1]);
                }
        }
        __syncthreads();
    }

    // Epilogue: p~ = exp(s/8), write + deterministic partial rowsums
#pragma unroll
    for (int t = 0; t < 2; t++) {
#pragma unroll
        for (int half = 0; half < 2; half++) {
            const int m = m0 + warp_m * 32 + t * 16 + g + half * 8;
            float rsum = 0.f;
#pragma unroll
            for (int u = 0; u < 4; u++) {
                const int n = n0 + warp_n * 32 + u * 8 + tk * 2;
                float p0 = __expf(acc[t][u][half * 2 + 0] * SCALE);
                float p1 = __expf(acc[t][u][half * 2 + 1] * SCALE);
                *(float2*)&P[(size_t)m * Ss + n] = make_float2(p0, p1);
                rsum += p0 + p1;
            }
            rsum += __shfl_xor_sync(0xffffffffu, rsum, 1);
            rsum += __shfl_xor_sync(0xffffffffu, rsum, 2);
            if (tk == 0)
                lpart[((size_t)(bh * Ss + m)) * 64 + blockIdx.x * 2 + warp_n] = rsum;
        }
    }
}

// ================ Reduce partial sums -> 1/l ================
__global__ __launch_bounds__(256) void reduce_l(const float* __restrict__ lpart,
                                                float* __restrict__ invl)
{
    int i = blockIdx.x * 256 + threadIdx.x;   // 0..BH*Ss-1
    const float* p = lpart + (size_t)i * 64;
    float s = 0.f;
#pragma unroll
    for (int j = 0; j < 64; j++) s += p[j];
    invl[i] = 1.f / s;
}

// ================ PV with in-loader normalization + P write-back ================
// O[i,dk] = sum_j (P~[i,j]*inv_l[i]) * Vt[dk,j];  writes normalized P back.
__global__ __launch_bounds__(256) void pv_norm_kernel(
    float* __restrict__ P, const float* __restrict__ Vt,
    float* __restrict__ O, const float* __restrict__ invl)
{
    const int bh = blockIdx.z;
    const int b_ = bh >> 3, h_ = bh & 7;
    P += (size_t)bh * Ss * Ss;
    const float* Vb = Vt + (size_t)bh * DKk * Ss;
    const int m0 = blockIdx.y * 128;

    const int tid = threadIdx.x;
    const int lane = tid & 31, wid = tid >> 5;
    const int warp_m = wid & 3, warp_n = wid >> 2;
    const int g = lane >> 2, tk = lane & 3;

    __shared__ uint32_t AsHi[128 * 20], AsLo[128 * 20];
    __shared__ uint32_t BsHi[64 * 20],  BsLo[64 * 20];

    float acc[2][4][4];
#pragma unroll
    for (int t = 0; t < 2; t++)
#pragma unroll
        for (int u = 0; u < 4; u++)
#pragma unroll
            for (int j = 0; j < 4; j++) acc[t][u][j] = 0.f;

    // per-slot fixed row -> inv factor
    float inva[4];
    int arow[4];
#pragma unroll
    for (int i = 0; i < 4; i++) {
        int v = tid + 256 * i;
        arow[i] = v >> 3;
        inva[i] = invl[bh * Ss + m0 + arow[i]];
    }

    float4 pa[4], pb[2];
#pragma unroll
    for (int i = 0; i < 4; i++) {
        int v = tid + 256 * i, c4 = v & 7;
        pa[i] = *(const float4*)&P[(size_t)(m0 + arow[i]) * Ss + c4 * 4];
    }
#pragma unroll
    for (int i = 0; i < 2; i++) {
        int v = tid + 256 * i, row = v >> 3, c4 = v & 7;
        pb[i] = *(const float4*)&Vb[(size_t)row * Ss + c4 * 4];
    }

    for (int c = 0; c < 64; c++) {
        const int k0 = c * 32;
#pragma unroll
        for (int i = 0; i < 4; i++) {
            int v = tid + 256 * i, c4 = v & 7;
            float f[4] = {pa[i].x * inva[i], pa[i].y * inva[i],
                          pa[i].z * inva[i], pa[i].w * inva[i]};
            // write back normalized P
            *(float4*)&P[(size_t)(m0 + arow[i]) * Ss + k0 + c4 * 4] =
                make_float4(f[0], f[1], f[2], f[3]);
            int w = arow[i] * 20 + c4 * 2;
            hilo(f[0], f[1], AsHi[w], AsLo[w]);
            hilo(f[2], f[3], AsHi[w + 1], AsLo[w + 1]);
        }
#pragma unroll
        for (int i = 0; i < 2; i++) {
            int v = tid + 256 * i, row = v >> 3, c4 = v & 7;
            float f[4] = {pb[i].x, pb[i].y, pb[i].z, pb[i].w};
            int w = row * 20 + c4 * 2;
            hilo(f[0], f[1], BsHi[w], BsLo[w]);
            hilo(f[2], f[3], BsHi[w + 1], BsLo[w + 1]);
        }
        __syncthreads();

        if (c + 1 < 64) {
            const int k1 = (c + 1) * 32;
#pragma unroll
            for (int i = 0; i < 4; i++) {
                int v = tid + 256 * i, c4 = v & 7;
                pa[i] = *(const float4*)&P[(size_t)(m0 + arow[i]) * Ss + k1 + c4 * 4];
            }
#pragma unroll
            for (int i = 0; i < 2; i++) {
                int v = tid + 256 * i, row = v >> 3, c4 = v & 7;
                pb[i] = *(const float4*)&Vb[(size_t)row * Ss + k1 + c4 * 4];
            }
        }

#pragma unroll
        for (int s = 0; s < 2; s++) {
            const int s8 = s * 8;
            uint32_t ah[2][4], al[2][4];
#pragma unroll
            for (int t = 0; t < 2; t++) {
                int r = (warp_m * 32 + t * 16 + g) * 20 + s8 + tk;
                ah[t][0] = AsHi[r];              al[t][0] = AsLo[r];
                ah[t][1] = AsHi[r + 8 * 20];     al[t][1] = AsLo[r + 8 * 20];
                ah[t][2] = AsHi[r + 4];          al[t][2] = AsLo[r + 4];
                ah[t][3] = AsHi[r + 8 * 20 + 4]; al[t][3] = AsLo[r + 8 * 20 + 4];
            }
            uint32_t bh2[4][2], bl2[4][2];
#pragma unroll
            for (int u = 0; u < 4; u++) {
                int r = (warp_n * 32 + u * 8 + g) * 20 + s8 + tk;
                bh2[u][0] = BsHi[r];     bl2[u][0] = BsLo[r];
                bh2[u][1] = BsHi[r + 4]; bl2[u][1] = BsLo[r + 4];
            }
#pragma unroll
            for (int t = 0; t < 2; t++)
#pragma unroll
                for (int u = 0; u < 4; u++) {
                    float* cc = acc[t][u];
                    mma_bf16(cc[0], cc[1], cc[2], cc[3],
                             ah[t][0], ah[t][1], ah[t][2], ah[t][3], bh2[u][0], bh2[u][1]);
                    mma_bf16(cc[0], cc[1], cc[2], cc[3],
                             ah[t][0], ah[t][1], ah[t][2], ah[t][3], bl2[u][0], bl2[u][1]);
                    mma_bf16(cc[0], cc[1], cc[2], cc[3],
                             al[t][0], al[t][1], al[t][2], al[t][3], bh2[u][0], bh2[u][1]);
                }
        }
        __syncthreads();
    }

#pragma unroll
    for (int t = 0; t < 2; t++) {
#pragma unroll
        for (int half = 0; half < 2; half++) {
            const int m = m0 + warp_m * 32 + t * 16 + g + half * 8;
#pragma unroll
            for (int u = 0; u < 4; u++) {
                const int n = warp_n * 32 + u * 8 + tk * 2;
                float v0 = acc[t][u][half * 2 + 0];
                float v1 = acc[t][u][half * 2 + 1];
                *(float2*)&O[((size_t)(b_ * Ss + m)) * Dd + h_ * DKk + n] = make_float2(v0, v1);
            }
        }
    }
}

// ===================== Launch =====================
extern "C" void kernel_launch(void* const* d_in, const int* in_sizes, int n_in,
                              void* d_out, int out_size)
{
    const float* query = (const float*)d_in[0];
    const float* key   = (const float*)d_in[1];
    const float* value = (const float*)d_in[2];
    const float* w_q   = (const float*)d_in[3];
    const float* w_k   = (const float*)d_in[4];
    const float* w_v   = (const float*)d_in[5];
    const float* w_o   = (const float*)d_in[6];

    float* out_main = (float*)d_out;
    float* p_attn   = out_main + (size_t)MM * Dd;

    float *Qp, *Kp, *Vp, *Op, *Lp, *Ip;
    cudaGetSymbolAddress((void**)&Qp, g_Q);
    cudaGetSymbolAddress((void**)&Kp, g_K);
    cudaGetSymbolAddress((void**)&Vp, g_Vt);
    cudaGetSymbolAddress((void**)&Op, g_O);
    cudaGetSymbolAddress((void**)&Lp, g_lpart);
    cudaGetSymbolAddress((void**)&Ip, g_invl);

    dim3 pj_grid(Dd / 64, MM / 128);          // (8, 32)
    mma_gemm<0><<<pj_grid, 256>>>(query, w_q, Qp, Dd, Dd, Dd);
    mma_gemm<0><<<pj_grid, 256>>>(key,   w_k, Kp, Dd, Dd, Dd);
    mma_gemm<1><<<pj_grid, 256>>>(value, w_v, Vp, Dd, Dd, Dd);

    dim3 sc_grid(Ss / 64, Ss / 128, BH);      // (32, 16, 16)
    scores_exp_kernel<<<sc_grid, 256>>>(Qp, Kp, p_attn, Lp);

    reduce_l<<<(BH * Ss) / 256, 256>>>(Lp, Ip);

    dim3 pv_grid(1, Ss / 128, BH);            // (1, 16, 16)
    pv_norm_kernel<<<pv_grid, 256>>>(p_attn, Vp, Op, Ip);

    mma_gemm<2><<<pj_grid, 256>>>(Op, w_o, out_main, Dd, Dd, Dd);
}